// round 3
// baseline (speedup 1.0000x reference)
#include <cuda_runtime.h>

// SPDUnVectorize: x[B, L] packed upper triangle (row-major, incl. diag) ->
// out[B, n, n] symmetric. B=1024, n=256, L=n(n+1)/2=32896.
//
// Stripe kernel: one block per (batch, 32-row stripe). Stage stripe in smem,
// stream out as one contiguous 32KB write for DRAM row-buffer locality.

#define NMAT   256
#define L_IN   32896
#define BATCH  1024
#define NSTRIPE 8            // 256 / 32
#define PADW   260           // padded smem row stride (words); 260*4 % 16 == 0

__device__ __forceinline__ int tri_off(int r) {
    // packed offset of row r's first element (column r)
    return r * NMAT - (r * (r - 1)) / 2;
}

__global__ __launch_bounds__(256, 6)
void spd_unvec_stripe(const float* __restrict__ in, float* __restrict__ out) {
    __shared__ float s[32][PADW];

    const int ti = blockIdx.x;         // stripe index 0..7
    const int b  = blockIdx.y;         // batch
    const int R  = ti * 32;            // first global row of stripe
    const int tid = threadIdx.x;

    const float* __restrict__ inb  = in  + (size_t)b * L_IN;
    float*       __restrict__ outb = out + (size_t)b * (NMAT * NMAT);

    // ---- Phase A: load this stripe's own packed rows (cols >= r). ----
    // The union of these segments is ONE contiguous input span -> every
    // fetched sector is consumed (no read amplification).
    #pragma unroll
    for (int lr = 0; lr < 32; lr++) {
        const int r   = R + lr;
        const int len = NMAT - r;              // cols r..255
        if (tid < len) {
            s[lr][r + tid] = inb[tri_off(r) + tid];
        }
    }

    // ---- Phase B: mirror tiles from stripes above (tj < ti). ----
    // Tile (tj, ti): rows r' in [32tj, 32tj+32), cols [R, R+32).
    // Coalesced loads (L2 hits: owned by sibling stripe tj, same wave);
    // transposed smem writes (4-way bank conflict, small volume).
    const int row8 = tid >> 3;                 // 0..31
    const int qc   = (tid & 7) << 2;           // 0,4,...,28
    for (int tj = 0; tj < ti; tj++) {
        const int rp   = tj * 32 + row8;               // source row r'
        const int base = tri_off(rp) - rp + R;         // packed idx of (rp, R)
        float v0 = inb[base + qc + 0];
        float v1 = inb[base + qc + 1];
        float v2 = inb[base + qc + 2];
        float v3 = inb[base + qc + 3];
        const int c2 = tj * 32 + row8;                 // dest col = r'
        s[qc + 0][c2] = v0;                            // dest row = local col
        s[qc + 1][c2] = v1;
        s[qc + 2][c2] = v2;
        s[qc + 3][c2] = v3;
    }

    __syncthreads();

    // ---- Phase C: mirror the diagonal tile in-place. ----
    // Read region (a,b) with b-R > a; write region (a,b) with b-R < a: disjoint.
    {
        float v0 = (qc + 0 < row8) ? s[qc + 0][R + row8] : 0.0f;
        float v1 = (qc + 1 < row8) ? s[qc + 1][R + row8] : 0.0f;
        float v2 = (qc + 2 < row8) ? s[qc + 2][R + row8] : 0.0f;
        float v3 = (qc + 3 < row8) ? s[qc + 3][R + row8] : 0.0f;
        if (qc + 0 < row8) s[row8][R + qc + 0] = v0;
        if (qc + 1 < row8) s[row8][R + qc + 1] = v1;
        if (qc + 2 < row8) s[row8][R + qc + 2] = v2;
        if (qc + 3 < row8) s[row8][R + qc + 3] = v3;
    }

    __syncthreads();

    // ---- Phase D: stream the full stripe out: contiguous 32KB per block. ----
    // LDS.128 conflict-free (128 consecutive words per warp), STG.128,
    // warp writes 512B sequential, block writes rows R..R+31 back-to-back.
    #pragma unroll
    for (int it = 0; it < 8; it++) {
        const int l   = it * 256 + tid;
        const int row = l >> 6;                // 0..31
        const int c4  = l & 63;                // float4 column 0..63
        float4 w = *reinterpret_cast<const float4*>(&s[row][c4 * 4]);
        *reinterpret_cast<float4*>(&outb[(R + row) * NMAT + c4 * 4]) = w;
    }
}

extern "C" void kernel_launch(void* const* d_in, const int* in_sizes, int n_in,
                              void* d_out, int out_size) {
    const float* in = (const float*)d_in[0];
    float* out = (float*)d_out;
    dim3 grid(NSTRIPE, BATCH);   // x fastest: all 8 stripes of a batch adjacent
    dim3 block(256);
    spd_unvec_stripe<<<grid, block>>>(in, out);
}

// round 4
// speedup vs baseline: 1.0824x; 1.0824x over previous
#include <cuda_runtime.h>

// SPDUnVectorize: x[B, L] packed upper triangle (row-major, incl. diag) ->
// out[B, n, n] symmetric. B=1024, n=256, L=n(n+1)/2=32896.

#define NMAT   256
#define L_IN   32896
#define BATCH  1024
#define TILE   32
#define NTROW  8
#define NTILES 36
#define PAD    33

__device__ __forceinline__ int tri_off(int r) {
    return r * NMAT - (r * (r - 1)) / 2;
}

__global__ __launch_bounds__(256, 8)
void spd_unvec_kernel(const float* __restrict__ in, float* __restrict__ out) {
    __shared__ float s[TILE][PAD];

    const int b = blockIdx.y;
    int t = blockIdx.x;

    int ti = 0;
    int rem = NTROW;
    while (t >= rem) { t -= rem; rem--; ti++; }
    const int tj = ti + t;

    const int w    = threadIdx.x >> 5;   // warp 0..7
    const int lane = threadIdx.x & 31;

    const float* __restrict__ inb  = in  + (size_t)b * L_IN;
    float*       __restrict__ outb = out + (size_t)b * (NMAT * NMAT);

    if (ti == tj) {
        // ---- Diagonal tile ----
        // Load: warp w handles rows 4w..4w+3; lane = column; only cols >= row.
        #pragma unroll
        for (int k = 0; k < 4; k++) {
            const int lr = w * 4 + k;
            const int r  = ti * TILE + lr;
            if (lane >= lr) {
                s[lr][lane] = __ldcs(&inb[tri_off(r) + lane - lr]);
            }
        }
        __syncthreads();
        const int row = threadIdx.x >> 3;
        const int qc  = (threadIdx.x & 7) << 2;
        float4 v;
        v.x = (qc + 0 >= row) ? s[row][qc + 0] : s[qc + 0][row];
        v.y = (qc + 1 >= row) ? s[row][qc + 1] : s[qc + 1][row];
        v.z = (qc + 2 >= row) ? s[row][qc + 2] : s[qc + 2][row];
        v.w = (qc + 3 >= row) ? s[row][qc + 3] : s[qc + 3][row];
        const int r = ti * TILE + row;
        __stcs(reinterpret_cast<float4*>(&outb[r * NMAT + ti * TILE + qc]), v);
    } else {
        // ---- Off-diagonal tile (ti < tj) ----
        // Load: warp w -> rows 4w..4w+3, lane -> column. Each LDG is 32
        // consecutive floats: every fetched sector fully consumed.
        #pragma unroll
        for (int k = 0; k < 4; k++) {
            const int lr = w * 4 + k;
            const int r  = ti * TILE + lr;
            s[lr][lane] = __ldcs(&inb[tri_off(r) - r + tj * TILE + lane]);
        }
        __syncthreads();

        // Store: warps 0-3 write the upper tile, warps 4-7 the mirror.
        // Each thread emits 32B (2x STG.128), fully coalesced full lines.
        const int t128 = (w & 3) * 32 + lane;    // 0..127
        const int row  = t128 >> 2;              // 0..31
        const int ch   = (t128 & 3) << 3;        // 0,8,16,24 (8-float chunk)

        if (w < 4) {
            float4 a, c;
            a.x = s[row][ch + 0]; a.y = s[row][ch + 1];
            a.z = s[row][ch + 2]; a.w = s[row][ch + 3];
            c.x = s[row][ch + 4]; c.y = s[row][ch + 5];
            c.z = s[row][ch + 6]; c.w = s[row][ch + 7];
            const int r = ti * TILE + row;
            float4* p = reinterpret_cast<float4*>(&outb[r * NMAT + tj * TILE + ch]);
            __stcs(p, a);
            __stcs(p + 1, c);
        } else {
            float4 a, c;
            a.x = s[ch + 0][row]; a.y = s[ch + 1][row];
            a.z = s[ch + 2][row]; a.w = s[ch + 3][row];
            c.x = s[ch + 4][row]; c.y = s[ch + 5][row];
            c.z = s[ch + 6][row]; c.w = s[ch + 7][row];
            const int r2 = tj * TILE + row;
            float4* p = reinterpret_cast<float4*>(&outb[r2 * NMAT + ti * TILE + ch]);
            __stcs(p, a);
            __stcs(p + 1, c);
        }
    }
}

extern "C" void kernel_launch(void* const* d_in, const int* in_sizes, int n_in,
                              void* d_out, int out_size) {
    const float* in = (const float*)d_in[0];
    float* out = (float*)d_out;
    dim3 grid(NTILES, BATCH);
    dim3 block(256);
    spd_unvec_kernel<<<grid, block>>>(in, out);
}

// round 5
// speedup vs baseline: 1.4931x; 1.3794x over previous
#include <cuda_runtime.h>

// SPDUnVectorize: x[B, L] packed upper triangle (row-major, incl. diag) ->
// out[B, n, n] symmetric. B=1024, n=256, L=n(n+1)/2=32896.
//
// One block = one upper-triangle 32x32 tile for TWO consecutive batches.
// Single __syncthreads(); 8 coalesced loads in flight per thread before it.

#define NMAT   256
#define L_IN   32896
#define BATCH  1024
#define TILE   32
#define NTROW  8
#define NTILES 36
#define PAD    33

__device__ __forceinline__ int tri_off(int r) {
    return r * NMAT - (r * (r - 1)) / 2;
}

__global__ __launch_bounds__(256, 8)
void spd_unvec_kernel(const float* __restrict__ in, float* __restrict__ out) {
    __shared__ float s0[TILE][PAD];
    __shared__ float s1[TILE][PAD];

    const int b0 = blockIdx.y * 2;
    int t = blockIdx.x;

    int ti = 0;
    int rem = NTROW;
    while (t >= rem) { t -= rem; rem--; ti++; }
    const int tj = ti + t;

    const int lane = threadIdx.x & 31;   // column within tile
    const int wy   = threadIdx.x >> 5;   // 0..7 (base row)

    const float* __restrict__ in0  = in  + (size_t)b0 * L_IN;
    const float* __restrict__ in1  = in0 + L_IN;
    float*       __restrict__ out0 = out + (size_t)b0 * (NMAT * NMAT);
    float*       __restrict__ out1 = out0 + (NMAT * NMAT);

    if (ti == tj) {
        // ---- Diagonal tile, both batches ----
        #pragma unroll
        for (int k = 0; k < 4; k++) {
            const int lr = wy + k * 8;
            const int r  = ti * TILE + lr;
            if (lane >= lr) {
                const int idx = tri_off(r) + lane - lr;
                s0[lr][lane] = in0[idx];
                s1[lr][lane] = in1[idx];
            }
        }
        __syncthreads();
        const int row = threadIdx.x >> 3;
        const int qc  = (threadIdx.x & 7) << 2;
        const int r   = ti * TILE + row;
        float4 v0, v1;
        #pragma unroll
        for (int k = 0; k < 4; k++) {
            const int c  = qc + k;
            const bool up = (c >= row);
            ((float*)&v0)[k] = up ? s0[row][c] : s0[c][row];
            ((float*)&v1)[k] = up ? s1[row][c] : s1[c][row];
        }
        *reinterpret_cast<float4*>(&out0[r * NMAT + ti * TILE + qc]) = v0;
        *reinterpret_cast<float4*>(&out1[r * NMAT + ti * TILE + qc]) = v1;
    } else {
        // ---- Off-diagonal tile (ti < tj), both batches ----
        // Warp = one row of 32 consecutive packed floats: fully coalesced.
        #pragma unroll
        for (int k = 0; k < 4; k++) {
            const int lr  = wy + k * 8;
            const int r   = ti * TILE + lr;
            const int idx = tri_off(r) - r + tj * TILE + lane;
            s0[lr][lane] = in0[idx];
            s1[lr][lane] = in1[idx];
        }
        __syncthreads();

        const int row = threadIdx.x >> 3;
        const int qc  = (threadIdx.x & 7) << 2;
        const int r   = ti * TILE + row;    // upper-tile row
        const int r2  = tj * TILE + row;    // mirror-tile row

        float4 u0, u1, m0, m1;
        #pragma unroll
        for (int k = 0; k < 4; k++) {
            const int c = qc + k;
            ((float*)&u0)[k] = s0[row][c];
            ((float*)&u1)[k] = s1[row][c];
            ((float*)&m0)[k] = s0[c][row];
            ((float*)&m1)[k] = s1[c][row];
        }
        *reinterpret_cast<float4*>(&out0[r  * NMAT + tj * TILE + qc]) = u0;
        *reinterpret_cast<float4*>(&out0[r2 * NMAT + ti * TILE + qc]) = m0;
        *reinterpret_cast<float4*>(&out1[r  * NMAT + tj * TILE + qc]) = u1;
        *reinterpret_cast<float4*>(&out1[r2 * NMAT + ti * TILE + qc]) = m1;
    }
}

extern "C" void kernel_launch(void* const* d_in, const int* in_sizes, int n_in,
                              void* d_out, int out_size) {
    const float* in = (const float*)d_in[0];
    float* out = (float*)d_out;
    dim3 grid(NTILES, BATCH / 2);
    dim3 block(256);
    spd_unvec_kernel<<<grid, block>>>(in, out);
}